// round 8
// baseline (speedup 1.0000x reference)
#include <cuda_runtime.h>
#include <cuda_bf16.h>
#include <math.h>
#include <stdint.h>

// Problem constants
#define B_   64
#define S_   196
#define E_   768
#define H_   4
#define HD_  192
#define M_   (B_*S_)        // 12544
#define NE_  (B_*S_*E_)     // 9,633,792
#define LN_N (S_*E_)        // 150,528
#define WN_  (E_*E_)
#define SKP  224            // padded seq
#define NBH  (B_*H_)        // 256
#define NCTA_G (49*6)       // gemm grid CTAs
#define NENT  (NCTA_G*3)    // pp entries

// ---------------- scratch (device globals) ----------------
__device__ __align__(256) float g_emb[NE_];
__device__ __align__(256) float g_op[NE_];
__device__ float g_pp1_s[NENT];
__device__ float g_pp1_q[NENT];
__device__ float g_pp2_s[NENT];
__device__ float g_pp2_q[NENT];
__device__ float g_mu[B_];
__device__ float g_rstd[B_];

__device__ __align__(256) __nv_bfloat16 g_ap_hi[NE_];
__device__ __align__(256) __nv_bfloat16 g_ap_lo[NE_];
__device__ __align__(256) __nv_bfloat16 g_h_hi[NE_];
__device__ __align__(256) __nv_bfloat16 g_h_lo[NE_];
__device__ __align__(256) __nv_bfloat16 g_q_hi[NE_];
__device__ __align__(256) __nv_bfloat16 g_q_lo[NE_];
__device__ __align__(256) __nv_bfloat16 g_k_hi[NE_];
__device__ __align__(256) __nv_bfloat16 g_k_lo[NE_];
__device__ __align__(256) __nv_bfloat16 g_vt_hi[NBH*HD_*SKP];
__device__ __align__(256) __nv_bfloat16 g_vt_lo[NBH*HD_*SKP];
__device__ __align__(256) __nv_bfloat16 g_at_hi[NBH*S_*SKP];
__device__ __align__(256) __nv_bfloat16 g_at_lo[NBH*S_*SKP];
__device__ __align__(256) __nv_bfloat16 g_o_hi[NE_];
__device__ __align__(256) __nv_bfloat16 g_o_lo[NE_];
__device__ __align__(256) __nv_bfloat16 g_w_hi[5][WN_];
__device__ __align__(256) __nv_bfloat16 g_w_lo[5][WN_];

// ============================================================================
// PTX helpers
// ============================================================================
__device__ __forceinline__ uint32_t smem_u32(const void* p) {
    uint32_t a;
    asm("{ .reg .u64 t; cvta.to.shared.u64 t, %1; cvt.u32.u64 %0, t; }"
        : "=r"(a) : "l"(p));
    return a;
}
__device__ __forceinline__ void ldsm_x4(uint32_t* r, uint32_t addr) {
    asm volatile("ldmatrix.sync.aligned.m8n8.x4.shared.b16 {%0,%1,%2,%3}, [%4];"
                 : "=r"(r[0]), "=r"(r[1]), "=r"(r[2]), "=r"(r[3]) : "r"(addr));
}
__device__ __forceinline__ void ldsm_x2(uint32_t* r, uint32_t addr) {
    asm volatile("ldmatrix.sync.aligned.m8n8.x2.shared.b16 {%0,%1}, [%2];"
                 : "=r"(r[0]), "=r"(r[1]) : "r"(addr));
}
__device__ __forceinline__ void mma16816(float* c, const uint32_t* a, const uint32_t* b) {
    asm volatile(
        "mma.sync.aligned.m16n8k16.row.col.f32.bf16.bf16.f32 "
        "{%0,%1,%2,%3}, {%4,%5,%6,%7}, {%8,%9}, {%0,%1,%2,%3};"
        : "+f"(c[0]), "+f"(c[1]), "+f"(c[2]), "+f"(c[3])
        : "r"(a[0]), "r"(a[1]), "r"(a[2]), "r"(a[3]), "r"(b[0]), "r"(b[1]));
}
__device__ __forceinline__ void cp16(uint32_t saddr, const void* gaddr) {
    asm volatile("cp.async.cg.shared.global [%0], [%1], 16;"
                 :: "r"(saddr), "l"(gaddr) : "memory");
}
#define CP_COMMIT() asm volatile("cp.async.commit_group;" ::: "memory")
#define CP_WAIT1()  asm volatile("cp.async.wait_group 1;" ::: "memory")
#define CP_WAIT0()  asm volatile("cp.async.wait_group 0;" ::: "memory")

__device__ __forceinline__ void split1(float x, __nv_bfloat16& hi, __nv_bfloat16& lo) {
    hi = __float2bfloat16(x);
    lo = __float2bfloat16(x - __bfloat162float(hi));
}

// ============================================================================
// HMMA bf16-split GEMM — shared-operand, 2-stage cp.async.
// CTA 256x128, K-chunk 64, 12 chunks, 3 terms per chunk.
// mode 0: fp32 C.    mode 1: split hi/lo.    mode 2: split + per-head transpose.
// mode 3: fp32 C + per-batch LN partials -> g_pp1.
// mode 4: fp32 (C=acc+bias+Res) + partials -> g_pp2.
// ============================================================================
#define ASTR 72
#define ROWB 144
#define A_SZ (256 * ROWB)
#define B_SZ (128 * ROWB)
#define STG_BYTES (2*A_SZ + 2*B_SZ)  // 110592
#define GEMM_SMEM (2 * STG_BYTES)    // 221184

__global__ __launch_bounds__(256, 1) void gemm_mma(
    const __nv_bfloat16* __restrict__ Ahi, const __nv_bfloat16* __restrict__ Alo,
    const __nv_bfloat16* __restrict__ Bhi, const __nv_bfloat16* __restrict__ Blo,
    const float* __restrict__ bias, float* __restrict__ C,
    __nv_bfloat16* __restrict__ Chi, __nv_bfloat16* __restrict__ Clo,
    const float* __restrict__ Res, int mode)
{
    extern __shared__ char smem[];
    const uint32_t sbase = smem_u32(smem);
    const int tid = threadIdx.x;
    const int wid = tid >> 5, lane = tid & 31;
    const int m0 = blockIdx.y * 256, n0 = blockIdx.x * 128;
    const int wm = (wid >> 1) * 64, wn = (wid & 1) * 64;
    const int lr = tid >> 3, lseg = tid & 7;

    float acc[4][8][4];
#pragma unroll
    for (int i = 0; i < 4; i++)
#pragma unroll
        for (int j = 0; j < 8; j++)
#pragma unroll
            for (int q = 0; q < 4; q++) acc[i][j][q] = 0.f;

    auto issue = [&](int c, int st) {
        const int k0 = c * 64 + lseg * 8;
        const uint32_t base = sbase + st * STG_BYTES;
#pragma unroll
        for (int i = 0; i < 8; i++) {
            const int row = i * 32 + lr;
            const size_t go = (size_t)(m0 + row) * E_ + k0;
            const uint32_t so = row * ROWB + lseg * 16;
            cp16(base + so, Ahi + go);
            cp16(base + A_SZ + so, Alo + go);
        }
#pragma unroll
        for (int i = 0; i < 4; i++) {
            const int row = i * 32 + lr;
            const size_t go = (size_t)(n0 + row) * E_ + k0;
            const uint32_t so = row * ROWB + lseg * 16;
            cp16(base + 2*A_SZ + so, Bhi + go);
            cp16(base + 2*A_SZ + B_SZ + so, Blo + go);
        }
    };

    const int arow = wm + (lane & 15);
    const int akoff = (lane >> 4) * 8;
    const int brow = wn + (lane & 7) + ((lane >> 4) << 3);
    const int bkoff = ((lane >> 3) & 1) * 8;

    issue(0, 0); CP_COMMIT();

    for (int c = 0; c < 12; c++) {
        const int st = c & 1;
        if (c + 1 < 12) { issue(c + 1, st ^ 1); CP_COMMIT(); CP_WAIT1(); }
        else CP_WAIT0();
        __syncthreads();
        const uint32_t aHi = sbase + st * STG_BYTES;
        const uint32_t aLo = aHi + A_SZ;
        const uint32_t bHi = aHi + 2*A_SZ;
        const uint32_t bLo = bHi + B_SZ;
#pragma unroll
        for (int ks = 0; ks < 4; ks++) {
            const int k = ks * 16;
            uint32_t afh[4][4], bfh[4][4];
#pragma unroll
            for (int mt = 0; mt < 4; mt++)
                ldsm_x4(afh[mt], aHi + ((arow + mt * 16) * ASTR + k + akoff) * 2);
#pragma unroll
            for (int nt2 = 0; nt2 < 4; nt2++)
                ldsm_x4(bfh[nt2], bHi + ((brow + nt2 * 16) * ASTR + k + bkoff) * 2);
#pragma unroll
            for (int mt = 0; mt < 4; mt++)
#pragma unroll
                for (int nt = 0; nt < 8; nt++)
                    mma16816(acc[mt][nt], afh[mt], &bfh[nt >> 1][(nt & 1) * 2]);
            {
                uint32_t afl[4][4];
#pragma unroll
                for (int mt = 0; mt < 4; mt++)
                    ldsm_x4(afl[mt], aLo + ((arow + mt * 16) * ASTR + k + akoff) * 2);
#pragma unroll
                for (int mt = 0; mt < 4; mt++)
#pragma unroll
                    for (int nt = 0; nt < 8; nt++)
                        mma16816(acc[mt][nt], afl[mt], &bfh[nt >> 1][(nt & 1) * 2]);
            }
            {
                uint32_t bfl[4][4];
#pragma unroll
                for (int nt2 = 0; nt2 < 4; nt2++)
                    ldsm_x4(bfl[nt2], bLo + ((brow + nt2 * 16) * ASTR + k + bkoff) * 2);
#pragma unroll
                for (int mt = 0; mt < 4; mt++)
#pragma unroll
                    for (int nt = 0; nt < 8; nt++)
                        mma16816(acc[mt][nt], afh[mt], &bfl[nt >> 1][(nt & 1) * 2]);
            }
        }
        __syncthreads();
    }

    const int erow = lane >> 2;
    const int ecol = (lane & 3) * 2;

    // LN partial accumulators (modes 3/4)
    float ls[3] = {0.f, 0.f, 0.f}, lq[3] = {0.f, 0.f, 0.f};
    int bidx0[4], bidx1[4];
    const int b0 = m0 / S_;
#pragma unroll
    for (int mt = 0; mt < 4; mt++) {
        const int r = m0 + wm + mt * 16 + erow;
        bidx0[mt] = r / S_ - b0;
        bidx1[mt] = (r + 8) / S_ - b0;
    }

#pragma unroll
    for (int mt = 0; mt < 4; mt++) {
#pragma unroll
        for (int nt = 0; nt < 8; nt++) {
            const int col = n0 + wn + nt * 8 + ecol;
            const float b0f = bias[col], b1f = bias[col + 1];
            const int r0 = m0 + wm + mt * 16 + erow;
            float v00 = acc[mt][nt][0] + b0f, v01 = acc[mt][nt][1] + b1f;
            float v10 = acc[mt][nt][2] + b0f, v11 = acc[mt][nt][3] + b1f;
            if (mode == 1) {
                __nv_bfloat16 h0, l0, h1, l1;
                split1(v00, h0, l0); split1(v01, h1, l1);
                size_t off = (size_t)r0 * E_ + col;
                *(__nv_bfloat162*)&Chi[off] = __nv_bfloat162(h0, h1);
                *(__nv_bfloat162*)&Clo[off] = __nv_bfloat162(l0, l1);
                split1(v10, h0, l0); split1(v11, h1, l1);
                off = (size_t)(r0 + 8) * E_ + col;
                *(__nv_bfloat162*)&Chi[off] = __nv_bfloat162(h0, h1);
                *(__nv_bfloat162*)&Clo[off] = __nv_bfloat162(l0, l1);
            } else if (mode == 2) {
                const int hh = col / HD_, d = col - hh * HD_;
#pragma unroll
                for (int rr = 0; rr < 2; rr++) {
                    const int r = r0 + rr * 8;
                    const int bb = r / S_, s = r - bb * S_;
                    const float va = rr ? v10 : v00;
                    const float vb = rr ? v11 : v01;
                    __nv_bfloat16 h0, l0;
                    size_t o0 = ((size_t)(bb * H_ + hh) * HD_ + d) * SKP + s;
                    split1(va, h0, l0); Chi[o0] = h0; Clo[o0] = l0;
                    split1(vb, h0, l0); Chi[o0 + SKP] = h0; Clo[o0 + SKP] = l0;
                }
            } else {
                if (mode == 4) {
                    float2 r0v = *(const float2*)&Res[(size_t)r0 * E_ + col];
                    float2 r1v = *(const float2*)&Res[(size_t)(r0 + 8) * E_ + col];
                    v00 += r0v.x; v01 += r0v.y; v10 += r1v.x; v11 += r1v.y;
                }
                *(float2*)&C[(size_t)r0 * E_ + col] = make_float2(v00, v01);
                *(float2*)&C[(size_t)(r0 + 8) * E_ + col] = make_float2(v10, v11);
                if (mode >= 3) {
                    ls[bidx0[mt]] += v00 + v01;
                    lq[bidx0[mt]] += v00 * v00 + v01 * v01;
                    ls[bidx1[mt]] += v10 + v11;
                    lq[bidx1[mt]] += v10 * v10 + v11 * v11;
                }
            }
        }
    }

    if (mode >= 3) {
        __shared__ float redp[8][6];
#pragma unroll
        for (int i = 0; i < 3; i++)
#pragma unroll
            for (int o = 16; o > 0; o >>= 1) {
                ls[i] += __shfl_xor_sync(0xFFFFFFFFu, ls[i], o);
                lq[i] += __shfl_xor_sync(0xFFFFFFFFu, lq[i], o);
            }
        if (lane == 0)
#pragma unroll
            for (int i = 0; i < 3; i++) { redp[wid][i] = ls[i]; redp[wid][i + 3] = lq[i]; }
        __syncthreads();
        if (tid == 0) {
            float os[3] = {0.f, 0.f, 0.f}, oq[3] = {0.f, 0.f, 0.f};
#pragma unroll
            for (int w = 0; w < 8; w++)
#pragma unroll
                for (int i = 0; i < 3; i++) { os[i] += redp[w][i]; oq[i] += redp[w][i + 3]; }
            const int cta = blockIdx.y * gridDim.x + blockIdx.x;
            float* ps = (mode == 3) ? g_pp1_s : g_pp2_s;
            float* pq = (mode == 3) ? g_pp1_q : g_pp2_q;
#pragma unroll
            for (int i = 0; i < 3; i++) { ps[cta * 3 + i] = os[i]; pq[cta * 3 + i] = oq[i]; }
        }
    }
}

// ============================================================================
// Fused scores + softmax. CTA = 128 rows x 224 cols (all keys). 8 warps,
// warp tile 64x56. cp.async 2-stage. Epilogue: row softmax, write bf16 hi/lo.
// ============================================================================
#define SC_AROW 80                   // row bytes (40 bf16)
#define SC_A_STG (128 * SC_AROW)     // 10240
#define SC_B_OFF (2 * SC_A_STG)      // 20480
#define SC_B_STG (224 * SC_AROW)     // 17920
#define SC_RED (SC_B_OFF + 2 * SC_B_STG)      // 56320
#define SC_REDS (SC_RED + 4 * 128 * 4)        // 58368
#define SC_SMEM (SC_REDS + 4 * 128 * 4)       // 60416

__global__ __launch_bounds__(256, 1) void scores_softmax()
{
    extern __shared__ char smem[];
    const uint32_t sbase = smem_u32(smem);
    const int bh = blockIdx.y;
    const int b = bh >> 2, h = bh & 3;
    const int tid = threadIdx.x;
    const int wid = tid >> 5, lane = tid & 31;
    const int m0 = blockIdx.x * 128;
    const int wm = (wid >> 2) * 64, wn = (wid & 3) * 56;
    const int lr = tid >> 2, lseg = tid & 3;

    float acc[4][7][4];
#pragma unroll
    for (int i = 0; i < 4; i++)
#pragma unroll
        for (int j = 0; j < 7; j++)
#pragma unroll
            for (int q = 0; q < 4; q++) acc[i][j][q] = 0.f;

    auto issue = [&](int c, int st) {
        const int seg = c / 6;
        const int k0 = (c - seg * 6) * 32 + lseg * 8;
        const __nv_bfloat16* Qs = (seg == 1) ? g_q_lo : g_q_hi;
        const __nv_bfloat16* Ks = (seg == 2) ? g_k_lo : g_k_hi;
        const uint32_t aB = sbase + st * SC_A_STG;
        const uint32_t bB = sbase + SC_B_OFF + st * SC_B_STG;
#pragma unroll
        for (int i = 0; i < 2; i++) {
            const int row = i * 64 + lr;
            const int m = m0 + row;
            const int mc = m < S_ ? m : S_ - 1;
            cp16(aB + row * SC_AROW + lseg * 16,
                 Qs + (size_t)(b * S_ + mc) * E_ + h * HD_ + k0);
        }
#pragma unroll
        for (int i = 0; i < 4; i++) {
            const int row = i * 64 + lr;
            if (row < SKP) {
                const int nc = row < S_ ? row : S_ - 1;
                cp16(bB + row * SC_AROW + lseg * 16,
                     Ks + (size_t)(b * S_ + nc) * E_ + h * HD_ + k0);
            }
        }
    };

    const int arow = wm + (lane & 15);
    const int akoff = (lane >> 4) * 8;
    const int brow = wn + (lane & 7);
    const int bkoff = ((lane >> 3) & 1) * 8;

    issue(0, 0); CP_COMMIT();

    for (int c = 0; c < 18; c++) {
        const int st = c & 1;
        if (c + 1 < 18) { issue(c + 1, st ^ 1); CP_COMMIT(); CP_WAIT1(); }
        else CP_WAIT0();
        __syncthreads();
        const uint32_t aS = sbase + st * SC_A_STG;
        const uint32_t bS = sbase + SC_B_OFF + st * SC_B_STG;
#pragma unroll
        for (int ks = 0; ks < 2; ks++) {
            const int k = ks * 16;
            uint32_t af[4][4], bf[7][2];
#pragma unroll
            for (int mt = 0; mt < 4; mt++)
                ldsm_x4(af[mt], aS + ((arow + mt * 16) * 40 + k + akoff) * 2);
#pragma unroll
            for (int nt = 0; nt < 7; nt++)
                ldsm_x2(bf[nt], bS + ((brow + nt * 8) * 40 + k + bkoff) * 2);
#pragma unroll
            for (int mt = 0; mt < 4; mt++)
#pragma unroll
                for (int nt = 0; nt < 7; nt++)
                    mma16816(acc[mt][nt], af[mt], bf[nt]);
        }
        __syncthreads();
    }

    // ---- softmax over rows ----
    const float scale = rsqrtf((float)HD_);
    const int erow = lane >> 2, ecol = (lane & 3) * 2;
    float* redm = (float*)(smem + SC_RED);
    float* reds = (float*)(smem + SC_REDS);
    const int wnidx = wid & 3;

    float rmax[4][2];
#pragma unroll
    for (int mt = 0; mt < 4; mt++) { rmax[mt][0] = -1e30f; rmax[mt][1] = -1e30f; }
#pragma unroll
    for (int mt = 0; mt < 4; mt++)
#pragma unroll
        for (int nt = 0; nt < 7; nt++)
#pragma unroll
            for (int q = 0; q < 4; q++) {
                const int col = wn + nt * 8 + ecol + (q & 1);
                float v = acc[mt][nt][q] * scale;
                if (col >= S_) v = -1e30f;
                acc[mt][nt][q] = v;
                rmax[mt][q >> 1] = fmaxf(rmax[mt][q >> 1], v);
            }
#pragma unroll
    for (int mt = 0; mt < 4; mt++)
#pragma unroll
        for (int rr = 0; rr < 2; rr++) {
            rmax[mt][rr] = fmaxf(rmax[mt][rr], __shfl_xor_sync(0xFFFFFFFFu, rmax[mt][rr], 1));
            rmax[mt][rr] = fmaxf(rmax[mt][rr], __shfl_xor_sync(0xFFFFFFFFu, rmax[mt][rr], 2));
        }
    if ((lane & 3) == 0)
#pragma unroll
        for (int mt = 0; mt < 4; mt++)
#pragma unroll
            for (int rr = 0; rr < 2; rr++)
                redm[wnidx * 128 + wm + mt * 16 + erow + rr * 8] = rmax[mt][rr];
    __syncthreads();
#pragma unroll
    for (int mt = 0; mt < 4; mt++)
#pragma unroll
        for (int rr = 0; rr < 2; rr++) {
            const int lrw = wm + mt * 16 + erow + rr * 8;
            float m = fmaxf(fmaxf(redm[lrw], redm[128 + lrw]),
                            fmaxf(redm[256 + lrw], redm[384 + lrw]));
            rmax[mt][rr] = m;
        }

    float rsum[4][2];
#pragma unroll
    for (int mt = 0; mt < 4; mt++) { rsum[mt][0] = 0.f; rsum[mt][1] = 0.f; }
#pragma unroll
    for (int mt = 0; mt < 4; mt++)
#pragma unroll
        for (int nt = 0; nt < 7; nt++)
#pragma unroll
            for (int q = 0; q < 4; q++) {
                float p = __expf(acc[mt][nt][q] - rmax[mt][q >> 1]);
                acc[mt][nt][q] = p;
                rsum[mt][q >> 1] += p;
            }
#pragma unroll
    for (int mt = 0; mt < 4; mt++)
#pragma unroll
        for (int rr = 0; rr < 2; rr++) {
            rsum[mt][rr] += __shfl_xor_sync(0xFFFFFFFFu, rsum[mt][rr], 1);
            rsum[mt][rr] += __shfl_xor_sync(0xFFFFFFFFu, rsum[mt][rr], 2);
        }
    __syncthreads();   // redm reads done before reds writes (same region sep, but order warps)
    if ((lane & 3) == 0)
#pragma unroll
        for (int mt = 0; mt < 4; mt++)
#pragma unroll
            for (int rr = 0; rr < 2; rr++)
                reds[wnidx * 128 + wm + mt * 16 + erow + rr * 8] = rsum[mt][rr];
    __syncthreads();

#pragma unroll
    for (int mt = 0; mt < 4; mt++) {
#pragma unroll
        for (int rr = 0; rr < 2; rr++) {
            const int lrw = wm + mt * 16 + erow + rr * 8;
            const int r = m0 + lrw;
            if (r >= S_) continue;
            const float tot = reds[lrw] + reds[128 + lrw] + reds[256 + lrw] + reds[384 + lrw];
            const float inv = 1.0f / tot;
            __nv_bfloat16* ah = g_at_hi + ((size_t)bh * S_ + r) * SKP;
            __nv_bfloat16* al = g_at_lo + ((size_t)bh * S_ + r) * SKP;
#pragma unroll
            for (int nt = 0; nt < 7; nt++) {
                const int col = wn + nt * 8 + ecol;
                const float p0 = acc[mt][nt][rr * 2 + 0] * inv;
                const float p1 = acc[mt][nt][rr * 2 + 1] * inv;
                __nv_bfloat16 h0, l0, h1, l1;
                split1(p0, h0, l0); split1(p1, h1, l1);
                *(__nv_bfloat162*)&ah[col] = __nv_bfloat162(h0, h1);
                *(__nv_bfloat162*)&al[col] = __nv_bfloat162(l0, l1);
            }
        }
    }
}

// ============================================================================
// AV via HMMA: 256 threads, CTA tile 128x64, warp tile 32x32. (unchanged)
// ============================================================================
#define SSTR 40
__global__ __launch_bounds__(256) void av_mma()
{
    __shared__ __nv_bfloat16 As[2][128][SSTR];
    __shared__ __nv_bfloat16 Bs[2][64][SSTR];
    const int bh = blockIdx.z;
    const int b = bh >> 2, h = bh & 3;
    const int tid = threadIdx.x;
    const int wid = tid >> 5, lane = tid & 31;
    const int m0 = blockIdx.y * 128, n0 = blockIdx.x * 64;
    const int wm = (wid >> 1) * 32, wn = (wid & 1) * 32;
    const int lrow = tid >> 1, lcol = (tid & 1) * 16;

    float acc[2][4][4];
#pragma unroll
    for (int i = 0; i < 2; i++)
#pragma unroll
        for (int j = 0; j < 4; j++)
#pragma unroll
            for (int q = 0; q < 4; q++) acc[i][j][q] = 0.f;

    const int mrow = m0 + lrow, mclamp = mrow < S_ ? mrow : S_ - 1;
    uint4 ra0, ra1, rb0, rb1;
    const bool loadB = (tid < 128);
    auto gload = [&](int c) {
        const int seg = c / 7;
        const int k0 = (c - seg * 7) * 32 + lcol;
        const __nv_bfloat16* A = (seg == 1) ? g_at_lo : g_at_hi;
        const __nv_bfloat16* ap = A + ((size_t)bh * S_ + mclamp) * SKP + k0;
        ra0 = *(const uint4*)ap; ra1 = *(const uint4*)(ap + 8);
        if (loadB) {
            const __nv_bfloat16* Bsrc = (seg == 2) ? g_vt_lo : g_vt_hi;
            const __nv_bfloat16* bp = Bsrc + ((size_t)bh * HD_ + n0 + lrow) * SKP + k0;
            rb0 = *(const uint4*)bp; rb1 = *(const uint4*)(bp + 8);
        }
    };
    auto sstore = [&](int st) {
        *(uint4*)&As[st][lrow][lcol] = ra0; *(uint4*)&As[st][lrow][lcol + 8] = ra1;
        if (loadB) {
            *(uint4*)&Bs[st][lrow][lcol] = rb0; *(uint4*)&Bs[st][lrow][lcol + 8] = rb1;
        }
    };

    const uint32_t aBase = smem_u32(&As[0][0][0]);
    const uint32_t bBase = smem_u32(&Bs[0][0][0]);
    const int arow = wm + (lane & 15);
    const int akoff = (lane >> 4) * 8;
    const int brow = wn + (lane & 7);
    const int bkoff = ((lane >> 3) & 1) * 8;

    gload(0); sstore(0);
    __syncthreads();
    for (int c = 0; c < 21; c++) {
        const int st = c & 1;
        if (c + 1 < 21) gload(c + 1);
        const uint32_t aS = aBase + st * (128 * SSTR * 2);
        const uint32_t bS = bBase + st * (64 * SSTR * 2);
#pragma unroll
        for (int ks = 0; ks < 2; ks++) {
            const int k = ks * 16;
            uint32_t af[2][4], bf[4][2];
#pragma unroll
            for (int mt = 0; mt < 2; mt++)
                ldsm_x4(af[mt], aS + ((arow + mt * 16) * SSTR + k + akoff) * 2);
#pragma unroll
            for (int nt = 0; nt < 4; nt++)
                ldsm_x2(bf[nt], bS + ((brow + nt * 8) * SSTR + k + bkoff) * 2);
#pragma unroll
            for (int mt = 0; mt < 2; mt++)
#pragma unroll
                for (int nt = 0; nt < 4; nt++)
                    mma16816(acc[mt][nt], af[mt], bf[nt]);
        }
        if (c + 1 < 21) sstore(st ^ 1);
        __syncthreads();
    }

    const int erow = lane >> 2, ecol = (lane & 3) * 2;
#pragma unroll
    for (int mt = 0; mt < 2; mt++) {
#pragma unroll
        for (int nt = 0; nt < 4; nt++) {
            const int col = n0 + wn + nt * 8 + ecol;
            const int r0 = m0 + wm + mt * 16 + erow;
#pragma unroll
            for (int rr = 0; rr < 2; rr++) {
                const int r = r0 + rr * 8;
                if (r >= S_) continue;
                const float va = acc[mt][nt][rr * 2 + 0];
                const float vb = acc[mt][nt][rr * 2 + 1];
                __nv_bfloat16 h0, l0, h1, l1;
                split1(va, h0, l0); split1(vb, h1, l1);
                const size_t off = ((size_t)(b * S_ + r)) * E_ + h * HD_ + col;
                *(__nv_bfloat162*)&g_o_hi[off] = __nv_bfloat162(h0, h1);
                *(__nv_bfloat162*)&g_o_lo[off] = __nv_bfloat162(l0, l1);
            }
        }
    }
}

// ============================================================================
// Splits
// ============================================================================
__global__ __launch_bounds__(256) void weight_split_all(
    const float* __restrict__ w0, const float* __restrict__ w1,
    const float* __restrict__ w2, const float* __restrict__ w3,
    const float* __restrict__ w4)
{
    const int gid = blockIdx.x * 256 + threadIdx.x;
    if (gid >= 5 * (WN_ / 4)) return;
    const int wsel = gid / (WN_ / 4);
    const int r = gid - wsel * (WN_ / 4);
    const float* src = (wsel == 0) ? w0 : (wsel == 1) ? w1 : (wsel == 2) ? w2
                     : (wsel == 3) ? w3 : w4;
    float4 v = *(const float4*)(src + (size_t)r * 4);
    __nv_bfloat16 h[4], l[4];
#pragma unroll
    for (int i = 0; i < 4; i++) split1((&v.x)[i], h[i], l[i]);
    __nv_bfloat16* hi = g_w_hi[wsel];
    __nv_bfloat16* lo = g_w_lo[wsel];
    *(__nv_bfloat162*)&hi[r * 4]     = __nv_bfloat162(h[0], h[1]);
    *(__nv_bfloat162*)&hi[r * 4 + 2] = __nv_bfloat162(h[2], h[3]);
    *(__nv_bfloat162*)&lo[r * 4]     = __nv_bfloat162(l[0], l[1]);
    *(__nv_bfloat162*)&lo[r * 4 + 2] = __nv_bfloat162(l[2], l[3]);
}

__global__ __launch_bounds__(256) void patch_split(
    const float* __restrict__ x, __nv_bfloat16* __restrict__ hi,
    __nv_bfloat16* __restrict__ lo)
{
    const int gid = blockIdx.x * 256 + threadIdx.x;
    if (gid >= NE_ / 4) return;
    const int m = gid / 192;
    const int k = (gid - m * 192) * 4;
    const int b = m / S_;
    const int s = m - b * S_;
    const int gy = s / 14, gx = s - gy * 14;
    const int c = k >> 8;
    const int py = (k >> 4) & 15;
    const int px = k & 15;
    const float* src = x + ((((size_t)b * 3 + c) * 224 + gy * 16 + py) * 224 + gx * 16 + px);
    float4 v = *(const float4*)src;
    const size_t o = (size_t)m * E_ + k;
    __nv_bfloat16 h[4], l[4];
#pragma unroll
    for (int i = 0; i < 4; i++) split1((&v.x)[i], h[i], l[i]);
    *(__nv_bfloat162*)&hi[o]     = __nv_bfloat162(h[0], h[1]);
    *(__nv_bfloat162*)&hi[o + 2] = __nv_bfloat162(h[2], h[3]);
    *(__nv_bfloat162*)&lo[o]     = __nv_bfloat162(l[0], l[1]);
    *(__nv_bfloat162*)&lo[o + 2] = __nv_bfloat162(l[2], l[3]);
}

__global__ __launch_bounds__(256) void vt_zero()
{
    const int gid = blockIdx.x * 256 + threadIdx.x;
    const int total = NBH * HD_ * (SKP - S_);
    if (gid >= total) return;
    const int row = gid / (SKP - S_);
    const int s = S_ + gid - row * (SKP - S_);
    g_vt_hi[(size_t)row * SKP + s] = __float2bfloat16(0.f);
    g_vt_lo[(size_t)row * SKP + s] = __float2bfloat16(0.f);
}

// ============================================================================
// LN finalize from per-CTA partials; apply kernels (vectorized)
// ============================================================================
__global__ void ln_finalize_pp(int sel)
{
    const int b = threadIdx.x;
    if (b >= B_) return;
    const float* ps = sel ? g_pp2_s : g_pp1_s;
    const float* pq = sel ? g_pp2_q : g_pp1_q;
    float s = 0.f, sq = 0.f;
    for (int e = 0; e < NENT; e++) {
        const int cta = e / 3;
        const int idx = e - cta * 3;
        const int y = cta / 6;
        const int batch = (y * 256) / S_ + idx;
        if (batch == b) { s += ps[e]; sq += pq[e]; }
    }
    const float inv_n = 1.0f / (float)LN_N;
    const float mu = s * inv_n;
    const float var = sq * inv_n - mu * mu;
    g_mu[b] = mu;
    g_rstd[b] = rsqrtf(var + 1e-5f);
}

__global__ __launch_bounds__(256) void ln_apply_split(
    const float* __restrict__ A, const float* __restrict__ w,
    const float* __restrict__ bias)
{
    const int gid = blockIdx.x * 256 + threadIdx.x;
    if (gid >= NE_ / 4) return;
    const int b = gid / (LN_N / 4);
    const int r4 = gid - b * (LN_N / 4);
    const float mu = g_mu[b], rs = g_rstd[b];
    float4 v = ((const float4*)A)[gid];
    float4 ww = ((const float4*)w)[r4];
    float4 bb = ((const float4*)bias)[r4];
    float o0 = (v.x - mu) * rs * ww.x + bb.x;
    float o1 = (v.y - mu) * rs * ww.y + bb.y;
    float o2 = (v.z - mu) * rs * ww.z + bb.z;
    float o3 = (v.w - mu) * rs * ww.w + bb.w;
    __nv_bfloat16 h[4], l[4];
    split1(o0, h[0], l[0]); split1(o1, h[1], l[1]);
    split1(o2, h[2], l[2]); split1(o3, h[3], l[3]);
    const size_t o = (size_t)gid * 4;
    *(__nv_bfloat162*)&g_h_hi[o]     = __nv_bfloat162(h[0], h[1]);
    *(__nv_bfloat162*)&g_h_hi[o + 2] = __nv_bfloat162(h[2], h[3]);
    *(__nv_bfloat162*)&g_h_lo[o]     = __nv_bfloat162(l[0], l[1]);
    *(__nv_bfloat162*)&g_h_lo[o + 2] = __nv_bfloat162(l[2], l[3]);
}

__global__ __launch_bounds__(256) void ln_apply(
    const float* __restrict__ A, const float* __restrict__ w,
    const float* __restrict__ bias, float* __restrict__ out)
{
    const int gid = blockIdx.x * 256 + threadIdx.x;
    if (gid >= NE_ / 4) return;
    const int b = gid / (LN_N / 4);
    const int r4 = gid - b * (LN_N / 4);
    const float mu = g_mu[b], rs = g_rstd[b];
    float4 v = ((const float4*)A)[gid];
    float4 ww = ((const float4*)w)[r4];
    float4 bb = ((const float4*)bias)[r4];
    float4 o;
    o.x = (v.x - mu) * rs * ww.x + bb.x;
    o.y = (v.y - mu) * rs * ww.y + bb.y;
    o.z = (v.z - mu) * rs * ww.z + bb.z;
    o.w = (v.w - mu) * rs * ww.w + bb.w;
    ((float4*)out)[gid] = o;
}

// ============================================================================
// Launch
// ============================================================================
extern "C" void kernel_launch(void* const* d_in, const int* in_sizes, int n_in,
                              void* d_out, int out_size)
{
    const float* x      = (const float*)d_in[0];
    const float* conv_w = (const float*)d_in[1];
    const float* conv_b = (const float*)d_in[2];
    const float* wq = (const float*)d_in[3];  const float* bq = (const float*)d_in[4];
    const float* wk = (const float*)d_in[5];  const float* bk = (const float*)d_in[6];
    const float* wv = (const float*)d_in[7];  const float* bv = (const float*)d_in[8];
    const float* wo = (const float*)d_in[9];  const float* bo = (const float*)d_in[10];
    const float* ln1w = (const float*)d_in[11]; const float* ln1b = (const float*)d_in[12];
    const float* ln2w = (const float*)d_in[13]; const float* ln2b = (const float*)d_in[14];
    float* out = (float*)d_out;

    float *emb, *op;
    cudaGetSymbolAddress((void**)&emb, g_emb);
    cudaGetSymbolAddress((void**)&op,  g_op);
    __nv_bfloat16 *aph, *apl, *hh, *hl, *qh, *ql, *kh, *kl, *vth, *vtl, *oh, *ol, *wh, *wl;
    cudaGetSymbolAddress((void**)&aph, g_ap_hi);
    cudaGetSymbolAddress((void**)&apl, g_ap_lo);
    cudaGetSymbolAddress((void**)&hh,  g_h_hi);
    cudaGetSymbolAddress((void**)&hl,  g_h_lo);
    cudaGetSymbolAddress((void**)&qh,  g_q_hi);
    cudaGetSymbolAddress((void**)&ql,  g_q_lo);
    cudaGetSymbolAddress((void**)&kh,  g_k_hi);
    cudaGetSymbolAddress((void**)&kl,  g_k_lo);
    cudaGetSymbolAddress((void**)&vth, g_vt_hi);
    cudaGetSymbolAddress((void**)&vtl, g_vt_lo);
    cudaGetSymbolAddress((void**)&oh,  g_o_hi);
    cudaGetSymbolAddress((void**)&ol,  g_o_lo);
    cudaGetSymbolAddress((void**)&wh,  g_w_hi);
    cudaGetSymbolAddress((void**)&wl,  g_w_lo);

    cudaFuncSetAttribute(gemm_mma, cudaFuncAttributeMaxDynamicSharedMemorySize, GEMM_SMEM);
    cudaFuncSetAttribute(scores_softmax, cudaFuncAttributeMaxDynamicSharedMemorySize, SC_SMEM);

    const dim3 gemm_grid(6, 49);
    const dim3 sc_grid(2, NBH);
    const dim3 av_grid(3, 2, NBH);
    const int  lna_blocks = (NE_ / 4) / 256;
    const int  ws_blocks = (5 * (WN_ / 4) + 255) / 256;
    const int  ps_blocks = (NE_ / 4 + 255) / 256;
    const int  vz_blocks = (NBH * HD_ * (SKP - S_) + 255) / 256;

    // 0. splits
    weight_split_all<<<ws_blocks, 256>>>(conv_w, wq, wk, wv, wo);
    patch_split<<<ps_blocks, 256>>>(x, aph, apl);
    vt_zero<<<vz_blocks, 256>>>();
    // 1. patch embedding -> emb (fp32) + LN1 partials
    gemm_mma<<<gemm_grid, 256, GEMM_SMEM>>>(
        aph, apl, wh + 0 * (size_t)WN_, wl + 0 * (size_t)WN_, conv_b, emb,
        nullptr, nullptr, nullptr, 3);
    // 2. LN1 finalize + apply -> h hi/lo
    ln_finalize_pp<<<1, 64>>>(0);
    ln_apply_split<<<lna_blocks, 256>>>(emb, ln1w, ln1b);
    // 3. QKV
    gemm_mma<<<gemm_grid, 256, GEMM_SMEM>>>(
        hh, hl, wh + 1 * (size_t)WN_, wl + 1 * (size_t)WN_, bq, nullptr, qh, ql, nullptr, 1);
    gemm_mma<<<gemm_grid, 256, GEMM_SMEM>>>(
        hh, hl, wh + 2 * (size_t)WN_, wl + 2 * (size_t)WN_, bk, nullptr, kh, kl, nullptr, 1);
    gemm_mma<<<gemm_grid, 256, GEMM_SMEM>>>(
        hh, hl, wh + 3 * (size_t)WN_, wl + 3 * (size_t)WN_, bv, nullptr, vth, vtl, nullptr, 2);
    // 4. attention: fused scores+softmax, then AV
    scores_softmax<<<sc_grid, 256, SC_SMEM>>>();
    av_mma<<<av_grid, 256>>>();
    // 5. output projection + residual add + LN2 partials -> op (= emb + o@Wo)
    gemm_mma<<<gemm_grid, 256, GEMM_SMEM>>>(
        oh, ol, wh + 4 * (size_t)WN_, wl + 4 * (size_t)WN_, bo, op, nullptr, nullptr, emb, 4);
    // 6. LN2 finalize + apply -> out
    ln_finalize_pp<<<1, 64>>>(1);
    ln_apply<<<lna_blocks, 256>>>(op, ln2w, ln2b, out);
}

// round 10
// speedup vs baseline: 1.0019x; 1.0019x over previous
#include <cuda_runtime.h>
#include <cuda_bf16.h>
#include <math.h>
#include <stdint.h>

// Problem constants
#define B_   64
#define S_   196
#define E_   768
#define H_   4
#define HD_  192
#define M_   (B_*S_)        // 12544
#define NE_  (B_*S_*E_)     // 9,633,792
#define LN_N (S_*E_)        // 150,528
#define WN_  (E_*E_)
#define SKP  224            // padded seq
#define NBH  (B_*H_)        // 256
#define NCTA_G (49*6)
#define NENT  (NCTA_G*3)

// ---------------- scratch (device globals) ----------------
__device__ __align__(256) float g_emb[NE_];
__device__ __align__(256) float g_op[NE_];
__device__ float g_pp1_s[NENT];
__device__ float g_pp1_q[NENT];
__device__ float g_pp2_s[NENT];
__device__ float g_pp2_q[NENT];
__device__ float g_mu[B_];
__device__ float g_rstd[B_];

__device__ __align__(256) __nv_bfloat16 g_ap_hi[NE_];
__device__ __align__(256) __nv_bfloat16 g_ap_lo[NE_];
__device__ __align__(256) __nv_bfloat16 g_h_hi[NE_];
__device__ __align__(256) __nv_bfloat16 g_h_lo[NE_];
__device__ __align__(256) __nv_bfloat16 g_q_hi[NE_];
__device__ __align__(256) __nv_bfloat16 g_q_lo[NE_];
__device__ __align__(256) __nv_bfloat16 g_k_hi[NE_];
__device__ __align__(256) __nv_bfloat16 g_k_lo[NE_];
__device__ __align__(256) __nv_bfloat16 g_vt_hi[NBH*HD_*SKP];
__device__ __align__(256) __nv_bfloat16 g_vt_lo[NBH*HD_*SKP];
__device__ __align__(256) __nv_bfloat16 g_at_hi[NBH*S_*SKP];
__device__ __align__(256) __nv_bfloat16 g_at_lo[NBH*S_*SKP];
__device__ __align__(256) __nv_bfloat16 g_o_hi[NE_];
__device__ __align__(256) __nv_bfloat16 g_o_lo[NE_];
__device__ __align__(256) __nv_bfloat16 g_w_hi[5][WN_];
__device__ __align__(256) __nv_bfloat16 g_w_lo[5][WN_];

// ============================================================================
// PTX helpers
// ============================================================================
__device__ __forceinline__ uint32_t smem_u32(const void* p) {
    uint32_t a;
    asm("{ .reg .u64 t; cvta.to.shared.u64 t, %1; cvt.u32.u64 %0, t; }"
        : "=r"(a) : "l"(p));
    return a;
}
__device__ __forceinline__ void ldsm_x4(uint32_t* r, uint32_t addr) {
    asm volatile("ldmatrix.sync.aligned.m8n8.x4.shared.b16 {%0,%1,%2,%3}, [%4];"
                 : "=r"(r[0]), "=r"(r[1]), "=r"(r[2]), "=r"(r[3]) : "r"(addr));
}
__device__ __forceinline__ void ldsm_x2(uint32_t* r, uint32_t addr) {
    asm volatile("ldmatrix.sync.aligned.m8n8.x2.shared.b16 {%0,%1}, [%2];"
                 : "=r"(r[0]), "=r"(r[1]) : "r"(addr));
}
__device__ __forceinline__ void mma16816(float* c, const uint32_t* a, const uint32_t* b) {
    asm volatile(
        "mma.sync.aligned.m16n8k16.row.col.f32.bf16.bf16.f32 "
        "{%0,%1,%2,%3}, {%4,%5,%6,%7}, {%8,%9}, {%0,%1,%2,%3};"
        : "+f"(c[0]), "+f"(c[1]), "+f"(c[2]), "+f"(c[3])
        : "r"(a[0]), "r"(a[1]), "r"(a[2]), "r"(a[3]), "r"(b[0]), "r"(b[1]));
}
__device__ __forceinline__ void cp16(uint32_t saddr, const void* gaddr) {
    asm volatile("cp.async.cg.shared.global [%0], [%1], 16;"
                 :: "r"(saddr), "l"(gaddr) : "memory");
}
#define CP_COMMIT() asm volatile("cp.async.commit_group;" ::: "memory")
#define CP_WAIT1()  asm volatile("cp.async.wait_group 1;" ::: "memory")
#define CP_WAIT0()  asm volatile("cp.async.wait_group 0;" ::: "memory")

__device__ __forceinline__ void split1(float x, __nv_bfloat16& hi, __nv_bfloat16& lo) {
    hi = __float2bfloat16(x);
    lo = __float2bfloat16(x - __bfloat162float(hi));
}

// ============================================================================
// HMMA bf16-split GEMM — shared-operand, 2-stage cp.async, MODE templated.
// CTA 256x128, K-chunk 64, 12 chunks, 3 terms per chunk.
// MODE 0: fp32 C.   MODE 1: split hi/lo.   MODE 2: split + per-head transpose.
// MODE 3: fp32 C + per-batch LN partials.  MODE 4: fp32 C=acc+bias+Res + partials.
// ============================================================================
#define ASTR 72
#define ROWB 144
#define A_SZ (256 * ROWB)
#define B_SZ (128 * ROWB)
#define STG_BYTES (2*A_SZ + 2*B_SZ)
#define GEMM_SMEM (2 * STG_BYTES)

template <int MODE>
__global__ __launch_bounds__(256, 1) void gemm_mma(
    const __nv_bfloat16* __restrict__ Ahi, const __nv_bfloat16* __restrict__ Alo,
    const __nv_bfloat16* __restrict__ Bhi, const __nv_bfloat16* __restrict__ Blo,
    const float* __restrict__ bias, float* __restrict__ C,
    __nv_bfloat16* __restrict__ Chi, __nv_bfloat16* __restrict__ Clo,
    const float* __restrict__ Res)
{
    extern __shared__ char smem[];
    const uint32_t sbase = smem_u32(smem);
    const int tid = threadIdx.x;
    const int wid = tid >> 5, lane = tid & 31;
    const int m0 = blockIdx.y * 256, n0 = blockIdx.x * 128;
    const int wm = (wid >> 1) * 64, wn = (wid & 1) * 64;
    const int lr = tid >> 3, lseg = tid & 7;

    float acc[4][8][4];
#pragma unroll
    for (int i = 0; i < 4; i++)
#pragma unroll
        for (int j = 0; j < 8; j++)
#pragma unroll
            for (int q = 0; q < 4; q++) acc[i][j][q] = 0.f;

    auto issue = [&](int c, int st) {
        const int k0 = c * 64 + lseg * 8;
        const uint32_t base = sbase + st * STG_BYTES;
#pragma unroll
        for (int i = 0; i < 8; i++) {
            const int row = i * 32 + lr;
            const size_t go = (size_t)(m0 + row) * E_ + k0;
            const uint32_t so = row * ROWB + lseg * 16;
            cp16(base + so, Ahi + go);
            cp16(base + A_SZ + so, Alo + go);
        }
#pragma unroll
        for (int i = 0; i < 4; i++) {
            const int row = i * 32 + lr;
            const size_t go = (size_t)(n0 + row) * E_ + k0;
            const uint32_t so = row * ROWB + lseg * 16;
            cp16(base + 2*A_SZ + so, Bhi + go);
            cp16(base + 2*A_SZ + B_SZ + so, Blo + go);
        }
    };

    const int arow = wm + (lane & 15);
    const int akoff = (lane >> 4) * 8;
    const int brow = wn + (lane & 7) + ((lane >> 4) << 3);
    const int bkoff = ((lane >> 3) & 1) * 8;

    issue(0, 0); CP_COMMIT();

    for (int c = 0; c < 12; c++) {
        const int st = c & 1;
        if (c + 1 < 12) { issue(c + 1, st ^ 1); CP_COMMIT(); CP_WAIT1(); }
        else CP_WAIT0();
        __syncthreads();
        const uint32_t aHi = sbase + st * STG_BYTES;
        const uint32_t aLo = aHi + A_SZ;
        const uint32_t bHi = aHi + 2*A_SZ;
        const uint32_t bLo = bHi + B_SZ;
#pragma unroll
        for (int ks = 0; ks < 4; ks++) {
            const int k = ks * 16;
            uint32_t afh[4][4], bfh[4][4];
#pragma unroll
            for (int mt = 0; mt < 4; mt++)
                ldsm_x4(afh[mt], aHi + ((arow + mt * 16) * ASTR + k + akoff) * 2);
#pragma unroll
            for (int nt2 = 0; nt2 < 4; nt2++)
                ldsm_x4(bfh[nt2], bHi + ((brow + nt2 * 16) * ASTR + k + bkoff) * 2);
#pragma unroll
            for (int mt = 0; mt < 4; mt++)
#pragma unroll
                for (int nt = 0; nt < 8; nt++)
                    mma16816(acc[mt][nt], afh[mt], &bfh[nt >> 1][(nt & 1) * 2]);
            {
                uint32_t afl[4][4];
#pragma unroll
                for (int mt = 0; mt < 4; mt++)
                    ldsm_x4(afl[mt], aLo + ((arow + mt * 16) * ASTR + k + akoff) * 2);
#pragma unroll
                for (int mt = 0; mt < 4; mt++)
#pragma unroll
                    for (int nt = 0; nt < 8; nt++)
                        mma16816(acc[mt][nt], afl[mt], &bfh[nt >> 1][(nt & 1) * 2]);
            }
            {
                uint32_t bfl[4][4];
#pragma unroll
                for (int nt2 = 0; nt2 < 4; nt2++)
                    ldsm_x4(bfl[nt2], bLo + ((brow + nt2 * 16) * ASTR + k + bkoff) * 2);
#pragma unroll
                for (int mt = 0; mt < 4; mt++)
#pragma unroll
                    for (int nt = 0; nt < 8; nt++)
                        mma16816(acc[mt][nt], afh[mt], &bfl[nt >> 1][(nt & 1) * 2]);
            }
        }
        __syncthreads();
    }

    const int erow = lane >> 2;
    const int ecol = (lane & 3) * 2;

    float ls[3], lq[3];
    int bidx0[4], bidx1[4];
    if (MODE >= 3) {
#pragma unroll
        for (int i = 0; i < 3; i++) { ls[i] = 0.f; lq[i] = 0.f; }
        const int b0 = m0 / S_;
#pragma unroll
        for (int mt = 0; mt < 4; mt++) {
            const int r = m0 + wm + mt * 16 + erow;
            bidx0[mt] = r / S_ - b0;
            bidx1[mt] = (r + 8) / S_ - b0;
        }
    }

#pragma unroll
    for (int mt = 0; mt < 4; mt++) {
#pragma unroll
        for (int nt = 0; nt < 8; nt++) {
            const int col = n0 + wn + nt * 8 + ecol;
            const float b0f = bias[col], b1f = bias[col + 1];
            const int r0 = m0 + wm + mt * 16 + erow;
            float v00 = acc[mt][nt][0] + b0f, v01 = acc[mt][nt][1] + b1f;
            float v10 = acc[mt][nt][2] + b0f, v11 = acc[mt][nt][3] + b1f;
            if (MODE == 1) {
                __nv_bfloat16 h0, l0, h1, l1;
                split1(v00, h0, l0); split1(v01, h1, l1);
                size_t off = (size_t)r0 * E_ + col;
                *(__nv_bfloat162*)&Chi[off] = __nv_bfloat162(h0, h1);
                *(__nv_bfloat162*)&Clo[off] = __nv_bfloat162(l0, l1);
                split1(v10, h0, l0); split1(v11, h1, l1);
                off = (size_t)(r0 + 8) * E_ + col;
                *(__nv_bfloat162*)&Chi[off] = __nv_bfloat162(h0, h1);
                *(__nv_bfloat162*)&Clo[off] = __nv_bfloat162(l0, l1);
            } else if (MODE == 2) {
                const int hh = col / HD_, d = col - hh * HD_;
#pragma unroll
                for (int rr = 0; rr < 2; rr++) {
                    const int r = r0 + rr * 8;
                    const int bb = r / S_, s = r - bb * S_;
                    const float va = rr ? v10 : v00;
                    const float vb = rr ? v11 : v01;
                    __nv_bfloat16 h0, l0;
                    size_t o0 = ((size_t)(bb * H_ + hh) * HD_ + d) * SKP + s;
                    split1(va, h0, l0); Chi[o0] = h0; Clo[o0] = l0;
                    split1(vb, h0, l0); Chi[o0 + SKP] = h0; Clo[o0 + SKP] = l0;
                }
            } else {
                if (MODE == 4) {
                    float2 r0v = *(const float2*)&Res[(size_t)r0 * E_ + col];
                    float2 r1v = *(const float2*)&Res[(size_t)(r0 + 8) * E_ + col];
                    v00 += r0v.x; v01 += r0v.y; v10 += r1v.x; v11 += r1v.y;
                }
                *(float2*)&C[(size_t)r0 * E_ + col] = make_float2(v00, v01);
                *(float2*)&C[(size_t)(r0 + 8) * E_ + col] = make_float2(v10, v11);
                if (MODE >= 3) {
                    ls[bidx0[mt]] += v00 + v01;
                    lq[bidx0[mt]] += v00 * v00 + v01 * v01;
                    ls[bidx1[mt]] += v10 + v11;
                    lq[bidx1[mt]] += v10 * v10 + v11 * v11;
                }
            }
        }
    }

    if (MODE >= 3) {
        __shared__ float redp[8][6];
#pragma unroll
        for (int i = 0; i < 3; i++)
#pragma unroll
            for (int o = 16; o > 0; o >>= 1) {
                ls[i] += __shfl_xor_sync(0xFFFFFFFFu, ls[i], o);
                lq[i] += __shfl_xor_sync(0xFFFFFFFFu, lq[i], o);
            }
        if (lane == 0)
#pragma unroll
            for (int i = 0; i < 3; i++) { redp[wid][i] = ls[i]; redp[wid][i + 3] = lq[i]; }
        __syncthreads();
        if (tid == 0) {
            float os[3] = {0.f, 0.f, 0.f}, oq[3] = {0.f, 0.f, 0.f};
#pragma unroll
            for (int w = 0; w < 8; w++)
#pragma unroll
                for (int i = 0; i < 3; i++) { os[i] += redp[w][i]; oq[i] += redp[w][i + 3]; }
            const int cta = blockIdx.y * gridDim.x + blockIdx.x;
            float* ps = (MODE == 3) ? g_pp1_s : g_pp2_s;
            float* pq = (MODE == 3) ? g_pp1_q : g_pp2_q;
#pragma unroll
            for (int i = 0; i < 3; i++) { ps[cta * 3 + i] = os[i]; pq[cta * 3 + i] = oq[i]; }
        }
    }
}

// ============================================================================
// Fused scores + softmax. CTA = 128 rows x 224 cols. 8 warps, warp tile 64x56.
// ============================================================================
#define SC_AROW 80
#define SC_A_STG (128 * SC_AROW)
#define SC_B_OFF (2 * SC_A_STG)
#define SC_B_STG (224 * SC_AROW)
#define SC_RED (SC_B_OFF + 2 * SC_B_STG)
#define SC_REDS (SC_RED + 4 * 128 * 4)
#define SC_SMEM (SC_REDS + 4 * 128 * 4)

__global__ __launch_bounds__(256, 1) void scores_softmax()
{
    extern __shared__ char smem[];
    const uint32_t sbase = smem_u32(smem);
    const int bh = blockIdx.y;
    const int b = bh >> 2, h = bh & 3;
    const int tid = threadIdx.x;
    const int wid = tid >> 5, lane = tid & 31;
    const int m0 = blockIdx.x * 128;
    const int wm = (wid >> 2) * 64, wn = (wid & 3) * 56;
    const int lr = tid >> 2, lseg = tid & 3;

    float acc[4][7][4];
#pragma unroll
    for (int i = 0; i < 4; i++)
#pragma unroll
        for (int j = 0; j < 7; j++)
#pragma unroll
            for (int q = 0; q < 4; q++) acc[i][j][q] = 0.f;

    auto issue = [&](int c, int st) {
        const int seg = c / 6;
        const int k0 = (c - seg * 6) * 32 + lseg * 8;
        const __nv_bfloat16* Qs = (seg == 1) ? g_q_lo : g_q_hi;
        const __nv_bfloat16* Ks = (seg == 2) ? g_k_lo : g_k_hi;
        const uint32_t aB = sbase + st * SC_A_STG;
        const uint32_t bB = sbase + SC_B_OFF + st * SC_B_STG;
#pragma unroll
        for (int i = 0; i < 2; i++) {
            const int row = i * 64 + lr;
            const int m = m0 + row;
            const int mc = m < S_ ? m : S_ - 1;
            cp16(aB + row * SC_AROW + lseg * 16,
                 Qs + (size_t)(b * S_ + mc) * E_ + h * HD_ + k0);
        }
#pragma unroll
        for (int i = 0; i < 4; i++) {
            const int row = i * 64 + lr;
            if (row < SKP) {
                const int nc = row < S_ ? row : S_ - 1;
                cp16(bB + row * SC_AROW + lseg * 16,
                     Ks + (size_t)(b * S_ + nc) * E_ + h * HD_ + k0);
            }
        }
    };

    const int arow = wm + (lane & 15);
    const int akoff = (lane >> 4) * 8;
    const int brow = wn + (lane & 7);
    const int bkoff = ((lane >> 3) & 1) * 8;

    issue(0, 0); CP_COMMIT();

    for (int c = 0; c < 18; c++) {
        const int st = c & 1;
        if (c + 1 < 18) { issue(c + 1, st ^ 1); CP_COMMIT(); CP_WAIT1(); }
        else CP_WAIT0();
        __syncthreads();
        const uint32_t aS = sbase + st * SC_A_STG;
        const uint32_t bS = sbase + SC_B_OFF + st * SC_B_STG;
#pragma unroll
        for (int ks = 0; ks < 2; ks++) {
            const int k = ks * 16;
            uint32_t af[4][4], bf[7][2];
#pragma unroll
            for (int mt = 0; mt < 4; mt++)
                ldsm_x4(af[mt], aS + ((arow + mt * 16) * 40 + k + akoff) * 2);
#pragma unroll
            for (int nt = 0; nt < 7; nt++)
                ldsm_x2(bf[nt], bS + ((brow + nt * 8) * 40 + k + bkoff) * 2);
#pragma unroll
            for (int mt = 0; mt < 4; mt++)
#pragma unroll
                for (int nt = 0; nt < 7; nt++)
                    mma16816(acc[mt][nt], af[mt], bf[nt]);
        }
        __syncthreads();
    }

    const float scale = rsqrtf((float)HD_);
    const int erow = lane >> 2, ecol = (lane & 3) * 2;
    float* redm = (float*)(smem + SC_RED);
    float* reds = (float*)(smem + SC_REDS);
    const int wnidx = wid & 3;

    float rmax[4][2];
#pragma unroll
    for (int mt = 0; mt < 4; mt++) { rmax[mt][0] = -1e30f; rmax[mt][1] = -1e30f; }
#pragma unroll
    for (int mt = 0; mt < 4; mt++)
#pragma unroll
        for (int nt = 0; nt < 7; nt++)
#pragma unroll
            for (int q = 0; q < 4; q++) {
                const int col = wn + nt * 8 + ecol + (q & 1);
                float v = acc[mt][nt][q] * scale;
                if (col >= S_) v = -1e30f;
                acc[mt][nt][q] = v;
                rmax[mt][q >> 1] = fmaxf(rmax[mt][q >> 1], v);
            }
#pragma unroll
    for (int mt = 0; mt < 4; mt++)
#pragma unroll
        for (int rr = 0; rr < 2; rr++) {
            rmax[mt][rr] = fmaxf(rmax[mt][rr], __shfl_xor_sync(0xFFFFFFFFu, rmax[mt][rr], 1));
            rmax[mt][rr] = fmaxf(rmax[mt][rr], __shfl_xor_sync(0xFFFFFFFFu, rmax[mt][rr], 2));
        }
    if ((lane & 3) == 0)
#pragma unroll
        for (int mt = 0; mt < 4; mt++)
#pragma unroll
            for (int rr = 0; rr < 2; rr++)
                redm[wnidx * 128 + wm + mt * 16 + erow + rr * 8] = rmax[mt][rr];
    __syncthreads();
#pragma unroll
    for (int mt = 0; mt < 4; mt++)
#pragma unroll
        for (int rr = 0; rr < 2; rr++) {
            const int lrw = wm + mt * 16 + erow + rr * 8;
            rmax[mt][rr] = fmaxf(fmaxf(redm[lrw], redm[128 + lrw]),
                                 fmaxf(redm[256 + lrw], redm[384 + lrw]));
        }

    float rsum[4][2];
#pragma unroll
    for (int mt = 0; mt < 4; mt++) { rsum[mt][0] = 0.f; rsum[mt][1] = 0.f; }
#pragma unroll
    for (int mt = 0; mt < 4; mt++)
#pragma unroll
        for (int nt = 0; nt < 7; nt++)
#pragma unroll
            for (int q = 0; q < 4; q++) {
                float p = __expf(acc[mt][nt][q] - rmax[mt][q >> 1]);
                acc[mt][nt][q] = p;
                rsum[mt][q >> 1] += p;
            }
#pragma unroll
    for (int mt = 0; mt < 4; mt++)
#pragma unroll
        for (int rr = 0; rr < 2; rr++) {
            rsum[mt][rr] += __shfl_xor_sync(0xFFFFFFFFu, rsum[mt][rr], 1);
            rsum[mt][rr] += __shfl_xor_sync(0xFFFFFFFFu, rsum[mt][rr], 2);
        }
    __syncthreads();
    if ((lane & 3) == 0)
#pragma unroll
        for (int mt = 0; mt < 4; mt++)
#pragma unroll
            for (int rr = 0; rr < 2; rr++)
                reds[wnidx * 128 + wm + mt * 16 + erow + rr * 8] = rsum[mt][rr];
    __syncthreads();

#pragma unroll
    for (int mt = 0; mt < 4; mt++) {
#pragma unroll
        for (int rr = 0; rr < 2; rr++) {
            const int lrw = wm + mt * 16 + erow + rr * 8;
            const int r = m0 + lrw;
            if (r >= S_) continue;
            const float tot = reds[lrw] + reds[128 + lrw] + reds[256 + lrw] + reds[384 + lrw];
            const float inv = 1.0f / tot;
            __nv_bfloat16* ah = g_at_hi + ((size_t)bh * S_ + r) * SKP;
            __nv_bfloat16* al = g_at_lo + ((size_t)bh * S_ + r) * SKP;
#pragma unroll
            for (int nt = 0; nt < 7; nt++) {
                const int col = wn + nt * 8 + ecol;
                const float p0 = acc[mt][nt][rr * 2 + 0] * inv;
                const float p1 = acc[mt][nt][rr * 2 + 1] * inv;
                __nv_bfloat16 h0, l0, h1, l1;
                split1(p0, h0, l0); split1(p1, h1, l1);
                *(__nv_bfloat162*)&ah[col] = __nv_bfloat162(h0, h1);
                *(__nv_bfloat162*)&al[col] = __nv_bfloat162(l0, l1);
            }
        }
    }
}

// ============================================================================
// AV via HMMA: 256 threads, CTA tile 128x64, warp tile 32x32.
// ============================================================================
#define SSTR 40
__global__ __launch_bounds__(256) void av_mma()
{
    __shared__ __nv_bfloat16 As[2][128][SSTR];
    __shared__ __nv_bfloat16 Bs[2][64][SSTR];
    const int bh = blockIdx.z;
    const int b = bh >> 2, h = bh & 3;
    const int tid = threadIdx.x;
    const int wid = tid >> 5, lane = tid & 31;
    const int m0 = blockIdx.y * 128, n0 = blockIdx.x * 64;
    const int wm = (wid >> 1) * 32, wn = (wid & 1) * 32;
    const int lrow = tid >> 1, lcol = (tid & 1) * 16;

    float acc[2][4][4];
#pragma unroll
    for (int i = 0; i < 2; i++)
#pragma unroll
        for (int j = 0; j < 4; j++)
#pragma unroll
            for (int q = 0; q < 4; q++) acc[i][j][q] = 0.f;

    const int mrow = m0 + lrow, mclamp = mrow < S_ ? mrow : S_ - 1;
    uint4 ra0, ra1, rb0, rb1;
    const bool loadB = (tid < 128);
    auto gload = [&](int c) {
        const int seg = c / 7;
        const int k0 = (c - seg * 7) * 32 + lcol;
        const __nv_bfloat16* A = (seg == 1) ? g_at_lo : g_at_hi;
        const __nv_bfloat16* ap = A + ((size_t)bh * S_ + mclamp) * SKP + k0;
        ra0 = *(const uint4*)ap; ra1 = *(const uint4*)(ap + 8);
        if (loadB) {
            const __nv_bfloat16* Bsrc = (seg == 2) ? g_vt_lo : g_vt_hi;
            const __nv_bfloat16* bp = Bsrc + ((size_t)bh * HD_ + n0 + lrow) * SKP + k0;
            rb0 = *(const uint4*)bp; rb1 = *(const uint4*)(bp + 8);
        }
    };
    auto sstore = [&](int st) {
        *(uint4*)&As[st][lrow][lcol] = ra0; *(uint4*)&As[st][lrow][lcol + 8] = ra1;
        if (loadB) {
            *(uint4*)&Bs[st][lrow][lcol] = rb0; *(uint4*)&Bs[st][lrow][lcol + 8] = rb1;
        }
    };

    const uint32_t aBase = smem_u32(&As[0][0][0]);
    const uint32_t bBase = smem_u32(&Bs[0][0][0]);
    const int arow = wm + (lane & 15);
    const int akoff = (lane >> 4) * 8;
    const int brow = wn + (lane & 7);
    const int bkoff = ((lane >> 3) & 1) * 8;

    gload(0); sstore(0);
    __syncthreads();
    for (int c = 0; c < 21; c++) {
        const int st = c & 1;
        if (c + 1 < 21) gload(c + 1);
        const uint32_t aS = aBase + st * (128 * SSTR * 2);
        const uint32_t bS = bBase + st * (64 * SSTR * 2);
#pragma unroll
        for (int ks = 0; ks < 2; ks++) {
            const int k = ks * 16;
            uint32_t af[2][4], bf[4][2];
#pragma unroll
            for (int mt = 0; mt < 2; mt++)
                ldsm_x4(af[mt], aS + ((arow + mt * 16) * SSTR + k + akoff) * 2);
#pragma unroll
            for (int nt = 0; nt < 4; nt++)
                ldsm_x2(bf[nt], bS + ((brow + nt * 8) * SSTR + k + bkoff) * 2);
#pragma unroll
            for (int mt = 0; mt < 2; mt++)
#pragma unroll
                for (int nt = 0; nt < 4; nt++)
                    mma16816(acc[mt][nt], af[mt], bf[nt]);
        }
        if (c + 1 < 21) sstore(st ^ 1);
        __syncthreads();
    }

    const int erow = lane >> 2, ecol = (lane & 3) * 2;
#pragma unroll
    for (int mt = 0; mt < 2; mt++) {
#pragma unroll
        for (int nt = 0; nt < 4; nt++) {
            const int col = n0 + wn + nt * 8 + ecol;
            const int r0 = m0 + wm + mt * 16 + erow;
#pragma unroll
            for (int rr = 0; rr < 2; rr++) {
                const int r = r0 + rr * 8;
                if (r >= S_) continue;
                const float va = acc[mt][nt][rr * 2 + 0];
                const float vb = acc[mt][nt][rr * 2 + 1];
                __nv_bfloat16 h0, l0, h1, l1;
                split1(va, h0, l0); split1(vb, h1, l1);
                const size_t off = ((size_t)(b * S_ + r)) * E_ + h * HD_ + col;
                *(__nv_bfloat162*)&g_o_hi[off] = __nv_bfloat162(h0, h1);
                *(__nv_bfloat162*)&g_o_lo[off] = __nv_bfloat162(l0, l1);
            }
        }
    }
}

// ============================================================================
// Splits
// ============================================================================
__global__ __launch_bounds__(256) void weight_split_all(
    const float* __restrict__ w0, const float* __restrict__ w1,
    const float* __restrict__ w2, const float* __restrict__ w3,
    const float* __restrict__ w4)
{
    const int gid = blockIdx.x * 256 + threadIdx.x;
    if (gid >= 5 * (WN_ / 4)) return;
    const int wsel = gid / (WN_ / 4);
    const int r = gid - wsel * (WN_ / 4);
    const float* src = (wsel == 0) ? w0 : (wsel == 1) ? w1 : (wsel == 2) ? w2
                     : (wsel == 3) ? w3 : w4;
    float4 v = *(const float4*)(src + (size_t)r * 4);
    __nv_bfloat16 h[4], l[4];
#pragma unroll
    for (int i = 0; i < 4; i++) split1((&v.x)[i], h[i], l[i]);
    __nv_bfloat16* hi = g_w_hi[wsel];
    __nv_bfloat16* lo = g_w_lo[wsel];
    *(__nv_bfloat162*)&hi[r * 4]     = __nv_bfloat162(h[0], h[1]);
    *(__nv_bfloat162*)&hi[r * 4 + 2] = __nv_bfloat162(h[2], h[3]);
    *(__nv_bfloat162*)&lo[r * 4]     = __nv_bfloat162(l[0], l[1]);
    *(__nv_bfloat162*)&lo[r * 4 + 2] = __nv_bfloat162(l[2], l[3]);
}

__global__ __launch_bounds__(256) void patch_split(
    const float* __restrict__ x, __nv_bfloat16* __restrict__ hi,
    __nv_bfloat16* __restrict__ lo)
{
    const int gid = blockIdx.x * 256 + threadIdx.x;
    if (gid >= NE_ / 4) return;
    const int m = gid / 192;
    const int k = (gid - m * 192) * 4;
    const int b = m / S_;
    const int s = m - b * S_;
    const int gy = s / 14, gx = s - gy * 14;
    const int c = k >> 8;
    const int py = (k >> 4) & 15;
    const int px = k & 15;
    const float* src = x + ((((size_t)b * 3 + c) * 224 + gy * 16 + py) * 224 + gx * 16 + px);
    float4 v = *(const float4*)src;
    const size_t o = (size_t)m * E_ + k;
    __nv_bfloat16 h[4], l[4];
#pragma unroll
    for (int i = 0; i < 4; i++) split1((&v.x)[i], h[i], l[i]);
    *(__nv_bfloat162*)&hi[o]     = __nv_bfloat162(h[0], h[1]);
    *(__nv_bfloat162*)&hi[o + 2] = __nv_bfloat162(h[2], h[3]);
    *(__nv_bfloat162*)&lo[o]     = __nv_bfloat162(l[0], l[1]);
    *(__nv_bfloat162*)&lo[o + 2] = __nv_bfloat162(l[2], l[3]);
}

__global__ __launch_bounds__(256) void vt_zero()
{
    const int gid = blockIdx.x * 256 + threadIdx.x;
    const int total = NBH * HD_ * (SKP - S_);
    if (gid >= total) return;
    const int row = gid / (SKP - S_);
    const int s = S_ + gid - row * (SKP - S_);
    g_vt_hi[(size_t)row * SKP + s] = __float2bfloat16(0.f);
    g_vt_lo[(size_t)row * SKP + s] = __float2bfloat16(0.f);
}

// ============================================================================
// LN finalize from per-CTA partials; apply kernels
// ============================================================================
__global__ void ln_finalize_pp(int sel)
{
    const int b = threadIdx.x;
    if (b >= B_) return;
    const float* ps = sel ? g_pp2_s : g_pp1_s;
    const float* pq = sel ? g_pp2_q : g_pp1_q;
    float s = 0.f, sq = 0.f;
    for (int e = 0; e < NENT; e++) {
        const int cta = e / 3;
        const int idx = e - cta * 3;
        const int y = cta / 6;
        const int batch = (y * 256) / S_ + idx;
        if (batch == b) { s += ps[e]; sq += pq[e]; }
    }
    const float inv_n = 1.0f / (float)LN_N;
    const float mu = s * inv_n;
    const float var = sq * inv_n - mu * mu;
    g_mu[b] = mu;
    g_rstd[b] = rsqrtf(var + 1e-5f);
}

__global__ __launch_bounds__(256) void ln_apply_split(
    const float* __restrict__ A, const float* __restrict__ w,
    const float* __restrict__ bias)
{
    const int gid = blockIdx.x * 256 + threadIdx.x;
    if (gid >= NE_ / 4) return;
    const int b = gid / (LN_N / 4);
    const int r4 = gid - b * (LN_N / 4);
    const float mu = g_mu[b], rs = g_rstd[b];
    float4 v = ((const float4*)A)[gid];
    float4 ww = ((const float4*)w)[r4];
    float4 bb = ((const float4*)bias)[r4];
    float o0 = (v.x - mu) * rs * ww.x + bb.x;
    float o1 = (v.y - mu) * rs * ww.y + bb.y;
    float o2 = (v.z - mu) * rs * ww.z + bb.z;
    float o3 = (v.w - mu) * rs * ww.w + bb.w;
    __nv_bfloat16 h[4], l[4];
    split1(o0, h[0], l[0]); split1(o1, h[1], l[1]);
    split1(o2, h[2], l[2]); split1(o3, h[3], l[3]);
    const size_t o = (size_t)gid * 4;
    *(__nv_bfloat162*)&g_h_hi[o]     = __nv_bfloat162(h[0], h[1]);
    *(__nv_bfloat162*)&g_h_hi[o + 2] = __nv_bfloat162(h[2], h[3]);
    *(__nv_bfloat162*)&g_h_lo[o]     = __nv_bfloat162(l[0], l[1]);
    *(__nv_bfloat162*)&g_h_lo[o + 2] = __nv_bfloat162(l[2], l[3]);
}

__global__ __launch_bounds__(256) void ln_apply(
    const float* __restrict__ A, const float* __restrict__ w,
    const float* __restrict__ bias, float* __restrict__ out)
{
    const int gid = blockIdx.x * 256 + threadIdx.x;
    if (gid >= NE_ / 4) return;
    const int b = gid / (LN_N / 4);
    const int r4 = gid - b * (LN_N / 4);
    const float mu = g_mu[b], rs = g_rstd[b];
    float4 v = ((const float4*)A)[gid];
    float4 ww = ((const float4*)w)[r4];
    float4 bb = ((const float4*)bias)[r4];
    float4 o;
    o.x = (v.x - mu) * rs * ww.x + bb.x;
    o.y = (v.y - mu) * rs * ww.y + bb.y;
    o.z = (v.z - mu) * rs * ww.z + bb.z;
    o.w = (v.w - mu) * rs * ww.w + bb.w;
    ((float4*)out)[gid] = o;
}

// ============================================================================
// Launch
// ============================================================================
extern "C" void kernel_launch(void* const* d_in, const int* in_sizes, int n_in,
                              void* d_out, int out_size)
{
    const float* x      = (const float*)d_in[0];
    const float* conv_w = (const float*)d_in[1];
    const float* conv_b = (const float*)d_in[2];
    const float* wq = (const float*)d_in[3];  const float* bq = (const float*)d_in[4];
    const float* wk = (const float*)d_in[5];  const float* bk = (const float*)d_in[6];
    const float* wv = (const float*)d_in[7];  const float* bv = (const float*)d_in[8];
    const float* wo = (const float*)d_in[9];  const float* bo = (const float*)d_in[10];
    const float* ln1w = (const float*)d_in[11]; const float* ln1b = (const float*)d_in[12];
    const float* ln2w = (const float*)d_in[13]; const float* ln2b = (const float*)d_in[14];
    float* out = (float*)d_out;

    float *emb, *op;
    cudaGetSymbolAddress((void**)&emb, g_emb);
    cudaGetSymbolAddress((void**)&op,  g_op);
    __nv_bfloat16 *aph, *apl, *hh, *hl, *qh, *ql, *kh, *kl, *vth, *vtl, *oh, *ol, *wh, *wl;
    cudaGetSymbolAddress((void**)&aph, g_ap_hi);
    cudaGetSymbolAddress((void**)&apl, g_ap_lo);
    cudaGetSymbolAddress((void**)&hh,  g_h_hi);
    cudaGetSymbolAddress((void**)&hl,  g_h_lo);
    cudaGetSymbolAddress((void**)&qh,  g_q_hi);
    cudaGetSymbolAddress((void**)&ql,  g_q_lo);
    cudaGetSymbolAddress((void**)&kh,  g_k_hi);
    cudaGetSymbolAddress((void**)&kl,  g_k_lo);
    cudaGetSymbolAddress((void**)&vth, g_vt_hi);
    cudaGetSymbolAddress((void**)&vtl, g_vt_lo);
    cudaGetSymbolAddress((void**)&oh,  g_o_hi);
    cudaGetSymbolAddress((void**)&ol,  g_o_lo);
    cudaGetSymbolAddress((void**)&wh,  g_w_hi);
    cudaGetSymbolAddress((void**)&wl,  g_w_lo);

    cudaFuncSetAttribute(gemm_mma<1>, cudaFuncAttributeMaxDynamicSharedMemorySize, GEMM_SMEM);
    cudaFuncSetAttribute(gemm_mma<2>, cudaFuncAttributeMaxDynamicSharedMemorySize, GEMM_SMEM);
    cudaFuncSetAttribute(gemm_mma<3>, cudaFuncAttributeMaxDynamicSharedMemorySize, GEMM_SMEM);
    cudaFuncSetAttribute(gemm_mma<4>, cudaFuncAttributeMaxDynamicSharedMemorySize, GEMM_SMEM);
    cudaFuncSetAttribute(scores_softmax, cudaFuncAttributeMaxDynamicSharedMemorySize, SC_SMEM);

    const dim3 gemm_grid(6, 49);
    const dim3 sc_grid(2, NBH);
    const dim3 av_grid(3, 2, NBH);
    const int  lna_blocks = (NE_ / 4) / 256;
    const int  ws_blocks = (5 * (WN_ / 4) + 255) / 256;
    const int  ps_blocks = (NE_ / 4 + 255) / 256;
    const int  vz_blocks = (NBH * HD_ * (SKP - S_) + 255) / 256;

    // 0. splits
    weight_split_all<<<ws_blocks, 256>>>(conv_w, wq, wk, wv, wo);
    patch_split<<<ps_blocks, 256>>>(x, aph, apl);
    vt_zero<<<vz_blocks, 256>>>();
    // 1. patch embedding -> emb (fp32) + LN1 partials
    gemm_mma<3><<<gemm_grid, 256, GEMM_SMEM>>>(
        aph, apl, wh + 0 * (size_t)WN_, wl + 0 * (size_t)WN_, conv_b, emb,
        nullptr, nullptr, nullptr);
    // 2. LN1 finalize + apply -> h hi/lo
    ln_finalize_pp<<<1, 64>>>(0);
    ln_apply_split<<<lna_blocks, 256>>>(emb, ln1w, ln1b);
    // 3. QKV
    gemm_mma<1><<<gemm_grid, 256, GEMM_SMEM>>>(
        hh, hl, wh + 1 * (size_t)WN_, wl + 1 * (size_t)WN_, bq, nullptr, qh, ql, nullptr);
    gemm_mma<1><<<gemm_grid, 256, GEMM_SMEM>>>(
        hh, hl, wh + 2 * (size_t)WN_, wl + 2 * (size_t)WN_, bk, nullptr, kh, kl, nullptr);
    gemm_mma<2><<<gemm_grid, 256, GEMM_SMEM>>>(
        hh, hl, wh + 3 * (size_t)WN_, wl + 3 * (size_t)WN_, bv, nullptr, vth, vtl, nullptr);
    // 4. attention: fused scores+softmax, then AV
    scores_softmax<<<sc_grid, 256, SC_SMEM>>>();
    av_mma<<<av_grid, 256>>>();
    // 5. output projection + residual add + LN2 partials -> op
    gemm_mma<4><<<gemm_grid, 256, GEMM_SMEM>>>(
        oh, ol, wh + 4 * (size_t)WN_, wl + 4 * (size_t)WN_, bo, op, nullptr, nullptr, emb);
    // 6. LN2 finalize + apply -> out
    ln_finalize_pp<<<1, 64>>>(1);
    ln_apply<<<lna_blocks, 256>>>(op, ln2w, ln2b, out);
}